// round 3
// baseline (speedup 1.0000x reference)
#include <cuda_runtime.h>
#include <cstddef>
#include <cstdint>

// Problem dims
#define B_    256
#define T_    100
#define IN_   128
#define H_    1024
#define OUT_  35
#define TB_   (B_ * T_)   // 25600 = rows of the big batched GEMMs

// ---------------- scratch (device globals; no allocation allowed) ----------
__device__ float g_xs[(size_t)TB_ * IN_];     // x transposed to [T,B,IN] and /15
__device__ float g_cur[(size_t)TB_ * H_];     // layer currents [T,B,H]
__device__ float g_cur4[(size_t)TB_ * OUT_];  // layer-4 currents [T,B,OUT]
__device__ float g_q1[H_ * IN_];
__device__ float g_q2[H_ * H_];
__device__ float g_q3[H_ * H_];
__device__ float g_q4[OUT_ * H_];

// ---------------- packed f32x2 helpers (ptxas never emits FFMA2 on its own) -
__device__ __forceinline__ uint64_t pack2(float lo, float hi) {
    uint64_t r;
    asm("mov.b64 %0, {%1, %2};" : "=l"(r) : "f"(lo), "f"(hi));
    return r;
}
__device__ __forceinline__ void unpack2(uint64_t v, float& lo, float& hi) {
    asm("mov.b64 {%0, %1}, %2;" : "=f"(lo), "=f"(hi) : "l"(v));
}
__device__ __forceinline__ void fma2(uint64_t& d, uint64_t a, uint64_t b) {
    asm("fma.rn.f32x2 %0, %1, %2, %0;" : "+l"(d) : "l"(a), "l"(b));
}

// ---------------- fake-quant (matches jnp: clip, round-half-even) ----------
__global__ void quant_kernel(const float* __restrict__ w, float* __restrict__ q,
                             int n, float wmin, float wmax, float scale) {
    int i = blockIdx.x * blockDim.x + threadIdx.x;
    if (i >= n) return;
    float wc = fminf(fmaxf(w[i], wmin), wmax);
    float t  = __fdiv_rn(__fsub_rn(wc, wmin), scale);
    q[i] = __fadd_rn(__fmul_rn(rintf(t), scale), wmin);
}

// ---------------- x: [B,T,IN] -> [T,B,IN], scaled by 1/15 ------------------
__global__ void prep_x_kernel(const float* __restrict__ x, float* __restrict__ xs) {
    int idx = blockIdx.x * blockDim.x + threadIdx.x;
    if (idx >= TB_ * IN_) return;
    int i  = idx % IN_;
    int rb = idx / IN_;        // = t*B + b
    int b  = rb % B_;
    int t  = rb / B_;
    xs[idx] = __fdiv_rn(x[((size_t)b * T_ + t) * IN_ + i], 15.0f);
}

// ---------------- tiled SGEMM: C[M,N] = A[M,K] @ W[N,K]^T ------------------
// 128x128 block tile, BK=16, 256 threads, 8x8 per-thread micro-tile,
// inner product via packed fma.rn.f32x2 (bit-identical to scalar fmaf).
#define BM 128
#define BN 128
#define BK 16

__global__ __launch_bounds__(256)
void gemm_nt_kernel(const float* __restrict__ A, const float* __restrict__ W,
                    float* __restrict__ C, int M, int N, int K) {
    __shared__ float As[BK][BM];
    __shared__ float Ws[BK][BN];

    const int tid  = threadIdx.x;
    const int tr   = tid >> 4;   // 0..15 (row group)
    const int tc   = tid & 15;   // 0..15 (col group)
    const int row0 = blockIdx.y * BM;
    const int col0 = blockIdx.x * BN;

    // 8x8 accumulator as 8x4 packed f32x2 (j pairs)
    uint64_t acc[8][4];
#pragma unroll
    for (int i = 0; i < 8; i++)
#pragma unroll
        for (int j = 0; j < 4; j++) acc[i][j] = 0ull;

    for (int k0 = 0; k0 < K; k0 += BK) {
        // ---- load A tile 128x16 (512 float4, 2 per thread); M,K tile-exact
#pragma unroll
        for (int l = 0; l < 2; l++) {
            int lin = tid + l * 256;
            int r   = lin >> 2;
            int c4  = (lin & 3) << 2;
            float4 v = *(const float4*)&A[(size_t)(row0 + r) * K + k0 + c4];
            As[c4 + 0][r] = v.x;
            As[c4 + 1][r] = v.y;
            As[c4 + 2][r] = v.z;
            As[c4 + 3][r] = v.w;
        }
        // ---- load W tile 128x16, guard rows (N=35 case)
#pragma unroll
        for (int l = 0; l < 2; l++) {
            int lin = tid + l * 256;
            int r   = lin >> 2;
            int c4  = (lin & 3) << 2;
            int wr  = col0 + r;
            float4 v = make_float4(0.f, 0.f, 0.f, 0.f);
            if (wr < N) v = *(const float4*)&W[(size_t)wr * K + k0 + c4];
            Ws[c4 + 0][r] = v.x;
            Ws[c4 + 1][r] = v.y;
            Ws[c4 + 2][r] = v.z;
            Ws[c4 + 3][r] = v.w;
        }
        __syncthreads();

#pragma unroll
        for (int k = 0; k < BK; k++) {
            float4 a0 = *(const float4*)&As[k][tr * 8];
            float4 a1 = *(const float4*)&As[k][tr * 8 + 4];
            float4 b0 = *(const float4*)&Ws[k][tc * 8];
            float4 b1 = *(const float4*)&Ws[k][tc * 8 + 4];

            uint64_t aa[8];
            aa[0] = pack2(a0.x, a0.x); aa[1] = pack2(a0.y, a0.y);
            aa[2] = pack2(a0.z, a0.z); aa[3] = pack2(a0.w, a0.w);
            aa[4] = pack2(a1.x, a1.x); aa[5] = pack2(a1.y, a1.y);
            aa[6] = pack2(a1.z, a1.z); aa[7] = pack2(a1.w, a1.w);

            uint64_t bb[4];
            bb[0] = pack2(b0.x, b0.y); bb[1] = pack2(b0.z, b0.w);
            bb[2] = pack2(b1.x, b1.y); bb[3] = pack2(b1.z, b1.w);

#pragma unroll
            for (int i = 0; i < 8; i++) {
#pragma unroll
                for (int j = 0; j < 4; j++) {
                    fma2(acc[i][j], aa[i], bb[j]);
                }
            }
        }
        __syncthreads();
    }

#pragma unroll
    for (int i = 0; i < 8; i++) {
        int row = row0 + tr * 8 + i;
        if (row >= M) continue;
#pragma unroll
        for (int j = 0; j < 4; j++) {
            float lo, hi;
            unpack2(acc[i][j], lo, hi);
            int col = col0 + tc * 8 + 2 * j;
            if (col < N)     C[(size_t)row * N + col]     = lo;
            if (col + 1 < N) C[(size_t)row * N + col + 1] = hi;
        }
    }
}

// ---------------- LIF scans (reset_delay semantics, thr=1) -----------------
__global__ void lif_sub_kernel(const float* __restrict__ cur, float* __restrict__ spk,
                               float beta, int n) {
    int idx = blockIdx.x * blockDim.x + threadIdx.x;
    if (idx >= n) return;
    float m = 0.0f;
    for (int t = 0; t < T_; t++) {
        float c     = cur[(size_t)t * n + idx];
        float reset = (m > 1.0f) ? 1.0f : 0.0f;
        float base  = __fadd_rn(__fmul_rn(beta, m), c);
        m = base - reset;                       // thr = 1
        spk[(size_t)t * n + idx] = (m > 1.0f) ? 1.0f : 0.0f;
    }
}

__global__ void lif_zero_kernel(const float* __restrict__ cur, float* __restrict__ spk,
                                float* __restrict__ mem, float beta, int n) {
    int idx = blockIdx.x * blockDim.x + threadIdx.x;
    if (idx >= n) return;
    float m = 0.0f;
    for (int t = 0; t < T_; t++) {
        float c    = cur[(size_t)t * n + idx];
        bool  rst  = (m > 1.0f);
        float base = __fadd_rn(__fmul_rn(beta, m), c);
        m = rst ? 0.0f : base;
        spk[(size_t)t * n + idx] = (m > 1.0f) ? 1.0f : 0.0f;
        mem[(size_t)t * n + idx] = m;
    }
}

// ---------------------------------------------------------------------------
extern "C" void kernel_launch(void* const* d_in, const int* in_sizes, int n_in,
                              void* d_out, int out_size) {
    const float* x  = (const float*)d_in[0];
    const float* w1 = (const float*)d_in[1];
    const float* w2 = (const float*)d_in[2];
    const float* w3 = (const float*)d_in[3];
    const float* w4 = (const float*)d_in[4];
    float* out = (float*)d_out;

    float *xs, *cur, *cur4, *q1, *q2, *q3, *q4;
    cudaGetSymbolAddress((void**)&xs,   g_xs);
    cudaGetSymbolAddress((void**)&cur,  g_cur);
    cudaGetSymbolAddress((void**)&cur4, g_cur4);
    cudaGetSymbolAddress((void**)&q1,   g_q1);
    cudaGetSymbolAddress((void**)&q2,   g_q2);
    cudaGetSymbolAddress((void**)&q3,   g_q3);
    cudaGetSymbolAddress((void**)&q4,   g_q4);

    const size_t SPK  = (size_t)TB_ * H_;    // 26,214,400
    const size_t SPK4 = (size_t)TB_ * OUT_;  //    896,000
    float* spk1 = out;
    float* spk2 = out + SPK;
    float* spk3 = out + 2 * SPK;
    float* spk4 = out + 3 * SPK;
    float* mem4 = out + 3 * SPK + SPK4;

    const float scale1 = (float)((0.5 - (-0.5)) / 15.0);
    const float scale2 = (float)((1.0 - 0.001) / 15.0);

    quant_kernel<<<(H_ * IN_ + 255) / 256, 256>>>(w1, q1, H_ * IN_, -0.5f, 0.5f, scale1);
    quant_kernel<<<(H_ * H_  + 255) / 256, 256>>>(w2, q2, H_ * H_,  0.001f, 1.0f, scale2);
    quant_kernel<<<(H_ * H_  + 255) / 256, 256>>>(w3, q3, H_ * H_,  0.001f, 1.0f, scale2);
    quant_kernel<<<(OUT_ * H_ + 255) / 256, 256>>>(w4, q4, OUT_ * H_, 0.001f, 1.0f, scale2);

    prep_x_kernel<<<(TB_ * IN_ + 255) / 256, 256>>>(x, xs);

    dim3 blk(256);
    dim3 gHid(H_ / BN, TB_ / BM);   // (8, 200)
    dim3 gOut(1, TB_ / BM);         // (1, 200)  N=35 fits one column tile

    gemm_nt_kernel<<<gHid, blk>>>(xs, q1, cur, TB_, H_, IN_);
    lif_sub_kernel<<<(B_ * H_ + 255) / 256, 256>>>(cur, spk1, 0.9f, B_ * H_);

    gemm_nt_kernel<<<gHid, blk>>>(spk1, q2, cur, TB_, H_, H_);
    lif_sub_kernel<<<(B_ * H_ + 255) / 256, 256>>>(cur, spk2, 0.85f, B_ * H_);

    gemm_nt_kernel<<<gHid, blk>>>(spk2, q3, cur, TB_, H_, H_);
    lif_sub_kernel<<<(B_ * H_ + 255) / 256, 256>>>(cur, spk3, 0.8f, B_ * H_);

    gemm_nt_kernel<<<gOut, blk>>>(spk3, q4, cur4, TB_, OUT_, H_);
    lif_zero_kernel<<<(B_ * OUT_ + 255) / 256, 256>>>(cur4, spk4, mem4, 0.95f, B_ * OUT_);

    (void)in_sizes; (void)n_in; (void)out_size;
}

// round 6
// speedup vs baseline: 3.0060x; 3.0060x over previous
#include <cuda_runtime.h>
#include <cuda_bf16.h>
#include <cstddef>
#include <cstdint>

// Problem dims
#define B_    256
#define T_    100
#define IN_   128
#define H_    1024
#define OUT_  35
#define TB_   (B_ * T_)   // 25600 rows of the batched GEMMs

// ---------------- scratch (device globals; no allocation allowed) ----------
__device__ __align__(128) float         g_xs[(size_t)TB_ * IN_];   // [T,B,IN]/15 fp32
__device__ __align__(128) float         g_q1[H_ * IN_];            // layer-1 fp32 quant weights
__device__ __align__(128) __nv_bfloat16 g_w2k[H_ * H_];
__device__ __align__(128) __nv_bfloat16 g_w2e[H_ * H_];
__device__ __align__(128) __nv_bfloat16 g_w3k[H_ * H_];
__device__ __align__(128) __nv_bfloat16 g_w3e[H_ * H_];
__device__ __align__(128) __nv_bfloat16 g_w4k[64 * H_];            // padded, zeros past 35
__device__ __align__(128) __nv_bfloat16 g_w4e[64 * H_];
__device__ __align__(128) float         g_cur[(size_t)TB_ * H_];   // D1
__device__ __align__(128) float         g_cur2[(size_t)TB_ * H_];  // D2
__device__ __align__(128) float         g_cur4[(size_t)TB_ * 64];
__device__ __align__(128) float         g_cur4b[(size_t)TB_ * 64];
__device__ __align__(128) __nv_bfloat16 g_spkb[(size_t)TB_ * H_];
__device__ __align__(128) float         g_R[TB_];

// ---------------- PTX helpers ----------------------------------------------
__device__ __forceinline__ uint32_t smem_u32(const void* p) {
    uint32_t a;
    asm("{ .reg .u64 t; cvta.to.shared.u64 t, %1; cvt.u32.u64 %0, t; }" : "=r"(a) : "l"(p));
    return a;
}
__device__ __forceinline__ void cp16(uint32_t s, const void* g) {
    asm volatile("cp.async.cg.shared.global [%0], [%1], 16;" :: "r"(s), "l"(g));
}
__device__ __forceinline__ void cp_commit() {
    asm volatile("cp.async.commit_group;" ::: "memory");
}
__device__ __forceinline__ void ldsm4(uint32_t& r0, uint32_t& r1, uint32_t& r2, uint32_t& r3,
                                      uint32_t a) {
    asm volatile("ldmatrix.sync.aligned.m8n8.x4.shared.b16 {%0,%1,%2,%3}, [%4];"
                 : "=r"(r0), "=r"(r1), "=r"(r2), "=r"(r3) : "r"(a));
}
__device__ __forceinline__ void mma16816(float* d, const uint32_t* a, const uint32_t* b) {
    asm volatile("mma.sync.aligned.m16n8k16.row.col.f32.bf16.bf16.f32 "
                 "{%0,%1,%2,%3}, {%4,%5,%6,%7}, {%8,%9}, {%0,%1,%2,%3};"
                 : "+f"(d[0]), "+f"(d[1]), "+f"(d[2]), "+f"(d[3])
                 : "r"(a[0]), "r"(a[1]), "r"(a[2]), "r"(a[3]), "r"(b[0]), "r"(b[1]));
}

// ---------------- HMMA GEMM: C[M,N] = A[M,K] @ Bm[N,K]^T -------------------
// BM=128, BK=64 (128B rows, XOR-swizzled), BN template (128 or 64).
// 256 threads / 8 warps, cp.async double buffer, ldmatrix fragments.
template<int BN>
__global__ __launch_bounds__(256)
void gemm_hmma(const __nv_bfloat16* __restrict__ A, const __nv_bfloat16* __restrict__ Bm,
               float* __restrict__ C, int M, int N, int K) {
    constexpr int ABYTES = 128 * 128;
    constexpr int BBYTES = BN * 128;
    constexpr int STAGE  = ABYTES + BBYTES;
    constexpr int WARPS_M = (BN == 128) ? 2 : 4;
    constexpr int MF = (BN == 128) ? 4 : 2;

    extern __shared__ __align__(1024) char smem[];
    const int tid = threadIdx.x;
    const int wid = tid >> 5, lid = tid & 31;
    const int row0 = blockIdx.y * 128, col0 = blockIdx.x * BN;
    const int wm = wid % WARPS_M, wn = wid / WARPS_M;
    const int warpM0 = wm * (128 / WARPS_M);
    const int warpN0 = wn * 32;
    const uint32_t sb = smem_u32(smem);

    const int NCH = K / 64;

    float acc[MF][4][4];
#pragma unroll
    for (int i = 0; i < MF; i++)
#pragma unroll
        for (int j = 0; j < 4; j++)
#pragma unroll
            for (int c = 0; c < 4; c++) acc[i][j][c] = 0.0f;

    auto issue = [&](int i) {
        const int k0 = i * 64;
        const uint32_t base = sb + (i & 1) * STAGE;
#pragma unroll
        for (int p = 0; p < 4; p++) {                 // A: 1024 16B packets
            int u = tid + p * 256;
            int r = u >> 3, c = u & 7;
            cp16(base + r * 128 + ((c ^ (r & 7)) << 4),
                 A + (size_t)(row0 + r) * K + k0 + c * 8);
        }
#pragma unroll
        for (int p = 0; p < BN * 8 / 256; p++) {      // B packets
            int u = tid + p * 256;
            int r = u >> 3, c = u & 7;
            cp16(base + ABYTES + r * 128 + ((c ^ (r & 7)) << 4),
                 Bm + (size_t)(col0 + r) * K + k0 + c * 8);
        }
        cp_commit();
    };

    issue(0);
    if (NCH > 1) issue(1);

    for (int i = 0; i < NCH; i++) {
        const uint32_t base = sb + (i & 1) * STAGE;
        if (i + 1 < NCH) asm volatile("cp.async.wait_group 1;" ::: "memory");
        else             asm volatile("cp.async.wait_group 0;" ::: "memory");
        __syncthreads();

#pragma unroll
        for (int j = 0; j < 4; j++) {                  // 4 k16 steps per 64-chunk
            uint32_t a[MF][4], b[4][2];
#pragma unroll
            for (int mf = 0; mf < MF; mf++) {
                int r = warpM0 + mf * 16 + (lid & 15);
                int c = 2 * j + (lid >> 4);
                ldsm4(a[mf][0], a[mf][1], a[mf][2], a[mf][3],
                      base + r * 128 + ((c ^ (r & 7)) << 4));
            }
#pragma unroll
            for (int h = 0; h < 2; h++) {
                int r = warpN0 + h * 16 + (lid & 7) + (((lid >> 4) & 1) << 3);
                int c = 2 * j + ((lid >> 3) & 1);
                uint32_t t0, t1, t2, t3;
                ldsm4(t0, t1, t2, t3,
                      base + ABYTES + r * 128 + ((c ^ (r & 7)) << 4));
                b[2 * h][0] = t0; b[2 * h][1] = t1;
                b[2 * h + 1][0] = t2; b[2 * h + 1][1] = t3;
            }
#pragma unroll
            for (int mf = 0; mf < MF; mf++)
#pragma unroll
                for (int nf = 0; nf < 4; nf++)
                    mma16816(acc[mf][nf], a[mf], b[nf]);
        }
        __syncthreads();
        if (i + 2 < NCH) issue(i + 2);
    }

#pragma unroll
    for (int mf = 0; mf < MF; mf++) {
        int r = row0 + warpM0 + mf * 16 + (lid >> 2);
#pragma unroll
        for (int nf = 0; nf < 4; nf++) {
            int cc = col0 + warpN0 + nf * 8 + (lid & 3) * 2;
            float2 v0 = {acc[mf][nf][0], acc[mf][nf][1]};
            float2 v1 = {acc[mf][nf][2], acc[mf][nf][3]};
            *(float2*)&C[(size_t)r * N + cc]       = v0;
            *(float2*)&C[(size_t)(r + 8) * N + cc] = v1;
        }
    }
}

// ---------------- fp32 SGEMM for layer 1 (R1-identical math) ---------------
#define BM 128
#define BN1 128
#define BK 16
__global__ __launch_bounds__(256)
void gemm_nt_kernel(const float* __restrict__ A, const float* __restrict__ W,
                    float* __restrict__ C, int M, int N, int K) {
    __shared__ float As[BK][BM];
    __shared__ float Ws[BK][BN1];
    const int tid  = threadIdx.x;
    const int tr   = tid >> 4;
    const int tc   = tid & 15;
    const int row0 = blockIdx.y * BM;
    const int col0 = blockIdx.x * BN1;

    float acc[8][8];
#pragma unroll
    for (int i = 0; i < 8; i++)
#pragma unroll
        for (int j = 0; j < 8; j++) acc[i][j] = 0.0f;

    for (int k0 = 0; k0 < K; k0 += BK) {
#pragma unroll
        for (int l = 0; l < 2; l++) {
            int lin = tid + l * 256;
            int r = lin >> 2, c4 = (lin & 3) << 2;
            float4 v = *(const float4*)&A[(size_t)(row0 + r) * K + k0 + c4];
            As[c4 + 0][r] = v.x; As[c4 + 1][r] = v.y;
            As[c4 + 2][r] = v.z; As[c4 + 3][r] = v.w;
        }
#pragma unroll
        for (int l = 0; l < 2; l++) {
            int lin = tid + l * 256;
            int r = lin >> 2, c4 = (lin & 3) << 2;
            float4 v = *(const float4*)&W[(size_t)(col0 + r) * K + k0 + c4];
            Ws[c4 + 0][r] = v.x; Ws[c4 + 1][r] = v.y;
            Ws[c4 + 2][r] = v.z; Ws[c4 + 3][r] = v.w;
        }
        __syncthreads();
#pragma unroll
        for (int k = 0; k < BK; k++) {
            float4 a0 = *(const float4*)&As[k][tr * 8];
            float4 a1 = *(const float4*)&As[k][tr * 8 + 4];
            float4 b0 = *(const float4*)&Ws[k][tc * 8];
            float4 b1 = *(const float4*)&Ws[k][tc * 8 + 4];
            float a[8] = {a0.x, a0.y, a0.z, a0.w, a1.x, a1.y, a1.z, a1.w};
            float b[8] = {b0.x, b0.y, b0.z, b0.w, b1.x, b1.y, b1.z, b1.w};
#pragma unroll
            for (int i = 0; i < 8; i++)
#pragma unroll
                for (int j = 0; j < 8; j++)
                    acc[i][j] = fmaf(a[i], b[j], acc[i][j]);
        }
        __syncthreads();
    }
#pragma unroll
    for (int i = 0; i < 8; i++) {
        int row = row0 + tr * 8 + i;
#pragma unroll
        for (int j = 0; j < 8; j++)
            C[(size_t)row * N + col0 + tc * 8 + j] = acc[i][j];
    }
}

// ---------------- quant kernels --------------------------------------------
__global__ void quant_kernel(const float* __restrict__ w, float* __restrict__ q,
                             int n, float wmin, float wmax, float scale) {
    int i = blockIdx.x * blockDim.x + threadIdx.x;
    if (i >= n) return;
    float wc = fminf(fmaxf(w[i], wmin), wmax);
    float t  = __fdiv_rn(__fsub_rn(wc, wmin), scale);
    q[i] = __fadd_rn(__fmul_rn(rintf(t), scale), wmin);
}

// k index (bf16-exact) + e = q - (wmin + k*scale) in DOUBLE (fp32 eval would
// be ~100% wrong: e is itself ~1 ulp of q), then bf16.
__global__ void quantke_kernel(const float* __restrict__ w,
                               __nv_bfloat16* __restrict__ kq, __nv_bfloat16* __restrict__ eq,
                               int n, int nsrc, float wmin, float wmax, float scale) {
    int i = blockIdx.x * blockDim.x + threadIdx.x;
    if (i >= n) return;
    float kf = 0.0f, e = 0.0f;
    if (i < nsrc) {
        float wc = fminf(fmaxf(w[i], wmin), wmax);
        kf = rintf(__fdiv_rn(__fsub_rn(wc, wmin), scale));
        float q = __fadd_rn(__fmul_rn(kf, scale), wmin);
        double ed = (double)q - (double)wmin - (double)scale * (double)kf;
        e = (float)ed;
    }
    kq[i] = __float2bfloat16_rn(kf);
    eq[i] = __float2bfloat16_rn(e);
}

// ---------------- x: [B,T,IN] -> [T,B,IN]/15 (fp32, R1-identical) ----------
__global__ void prep_x_kernel(const float* __restrict__ x, float* __restrict__ xs) {
    int idx = blockIdx.x * blockDim.x + threadIdx.x;
    if (idx >= TB_ * IN_) return;
    int i  = idx % IN_;
    int rb = idx / IN_;
    int b  = rb % B_;
    int t  = rb / B_;
    xs[idx] = __fdiv_rn(x[((size_t)b * T_ + t) * IN_ + i], 15.0f);
}

// ---------------- rowsum of bf16 spikes (exact integers) -------------------
__global__ void rowsum_b_kernel(const __nv_bfloat16* __restrict__ S, float* __restrict__ R) {
    int w = (blockIdx.x * blockDim.x + threadIdx.x) >> 5;
    int l = threadIdx.x & 31;
    if (w >= TB_) return;
    const uint4* p = (const uint4*)(S + (size_t)w * H_);
    float s = 0.0f;
#pragma unroll
    for (int i = 0; i < 4; i++) {
        uint4 v = p[l + i * 32];
        const __nv_bfloat16* h = (const __nv_bfloat16*)&v;
#pragma unroll
        for (int c = 0; c < 8; c++) s += __bfloat162float(h[c]);
    }
#pragma unroll
    for (int o = 16; o; o >>= 1) s += __shfl_xor_sync(0xffffffffu, s, o);
    if (l == 0) R[w] = s;
}

// ---------------- LIF scans ------------------------------------------------
// Layer 1: direct fp32 currents (R1-identical)
__global__ void lif_sub1_kernel(const float* __restrict__ cur, float* __restrict__ spk,
                                __nv_bfloat16* __restrict__ spkb, float beta, int n) {
    int idx = blockIdx.x * blockDim.x + threadIdx.x;
    if (idx >= n) return;
    float m = 0.0f;
    for (int t = 0; t < T_; t++) {
        float c     = cur[(size_t)t * n + idx];
        float reset = (m > 1.0f) ? 1.0f : 0.0f;
        float base  = __fadd_rn(__fmul_rn(beta, m), c);
        m = base - reset;
        float s = (m > 1.0f) ? 1.0f : 0.0f;
        spk[(size_t)t * n + idx]  = s;
        spkb[(size_t)t * n + idx] = __float2bfloat16_rn(s);
    }
}

// Layers 2,3: cur = scale*D1 + wmin*R + D2
__global__ void lif_sub2_kernel(const float* __restrict__ D1, const float* __restrict__ D2,
                                const float* __restrict__ R,
                                float* __restrict__ spk, __nv_bfloat16* __restrict__ spkb,
                                float beta, float scale, float wmin) {
    int idx = blockIdx.x * blockDim.x + threadIdx.x;
    if (idx >= B_ * H_) return;
    int b = idx / H_, h = idx % H_;
    float m = 0.0f;
    for (int t = 0; t < T_; t++) {
        size_t mm = (size_t)t * B_ + b;
        float c = fmaf(scale, D1[mm * H_ + h], fmaf(wmin, R[mm], D2[mm * H_ + h]));
        float reset = (m > 1.0f) ? 1.0f : 0.0f;
        float base  = __fadd_rn(__fmul_rn(beta, m), c);
        m = base - reset;
        float s = (m > 1.0f) ? 1.0f : 0.0f;
        spk[(size_t)t * (B_ * H_) + idx]  = s;
        spkb[(size_t)t * (B_ * H_) + idx] = __float2bfloat16_rn(s);
    }
}

__global__ void lif_zero2_kernel(const float* __restrict__ D1, const float* __restrict__ D2,
                                 const float* __restrict__ R,
                                 float* __restrict__ spk, float* __restrict__ mem,
                                 float beta, float scale, float wmin) {
    int idx = blockIdx.x * blockDim.x + threadIdx.x;
    if (idx >= B_ * OUT_) return;
    int b = idx / OUT_, h = idx % OUT_;
    float m = 0.0f;
    for (int t = 0; t < T_; t++) {
        size_t mm = (size_t)t * B_ + b;
        float c = fmaf(scale, D1[mm * 64 + h], fmaf(wmin, R[mm], D2[mm * 64 + h]));
        bool  rst  = (m > 1.0f);
        float base = __fadd_rn(__fmul_rn(beta, m), c);
        m = rst ? 0.0f : base;
        spk[(size_t)t * (B_ * OUT_) + idx] = (m > 1.0f) ? 1.0f : 0.0f;
        mem[(size_t)t * (B_ * OUT_) + idx] = m;
    }
}

// ---------------------------------------------------------------------------
extern "C" void kernel_launch(void* const* d_in, const int* in_sizes, int n_in,
                              void* d_out, int out_size) {
    const float* x  = (const float*)d_in[0];
    const float* w1 = (const float*)d_in[1];
    const float* w2 = (const float*)d_in[2];
    const float* w3 = (const float*)d_in[3];
    const float* w4 = (const float*)d_in[4];
    float* out = (float*)d_out;

    float *xs, *q1, *cur, *cur2, *cur4, *cur4b, *R;
    __nv_bfloat16 *w2k, *w2e, *w3k, *w3e, *w4k, *w4e, *spkb;
    cudaGetSymbolAddress((void**)&xs, g_xs);     cudaGetSymbolAddress((void**)&q1, g_q1);
    cudaGetSymbolAddress((void**)&w2k, g_w2k);   cudaGetSymbolAddress((void**)&w2e, g_w2e);
    cudaGetSymbolAddress((void**)&w3k, g_w3k);   cudaGetSymbolAddress((void**)&w3e, g_w3e);
    cudaGetSymbolAddress((void**)&w4k, g_w4k);   cudaGetSymbolAddress((void**)&w4e, g_w4e);
    cudaGetSymbolAddress((void**)&cur, g_cur);   cudaGetSymbolAddress((void**)&cur2, g_cur2);
    cudaGetSymbolAddress((void**)&cur4, g_cur4); cudaGetSymbolAddress((void**)&cur4b, g_cur4b);
    cudaGetSymbolAddress((void**)&spkb, g_spkb); cudaGetSymbolAddress((void**)&R, g_R);

    const size_t SPK  = (size_t)TB_ * H_;
    const size_t SPK4 = (size_t)TB_ * OUT_;
    float* spk1 = out;
    float* spk2 = out + SPK;
    float* spk3 = out + 2 * SPK;
    float* spk4 = out + 3 * SPK;
    float* mem4 = out + 3 * SPK + SPK4;

    const float scale1 = (float)((0.5 - (-0.5)) / 15.0);
    const float scale2 = (float)((1.0 - 0.001) / 15.0);

    const int SM128 = 2 * (128 * 128 + 128 * 128);   // 65536
    const int SM64  = 2 * (128 * 128 + 64 * 128);    // 49152
    cudaFuncSetAttribute(gemm_hmma<128>, cudaFuncAttributeMaxDynamicSharedMemorySize, SM128);
    cudaFuncSetAttribute(gemm_hmma<64>,  cudaFuncAttributeMaxDynamicSharedMemorySize, SM64);

    // ---- prep
    quant_kernel<<<(H_ * IN_ + 255) / 256, 256>>>(w1, q1, H_ * IN_, -0.5f, 0.5f, scale1);
    quantke_kernel<<<(H_ * H_ + 255) / 256, 256>>>(w2, w2k, w2e, H_ * H_, H_ * H_, 0.001f, 1.0f, scale2);
    quantke_kernel<<<(H_ * H_ + 255) / 256, 256>>>(w3, w3k, w3e, H_ * H_, H_ * H_, 0.001f, 1.0f, scale2);
    quantke_kernel<<<(64 * H_ + 255) / 256, 256>>>(w4, w4k, w4e, 64 * H_, OUT_ * H_, 0.001f, 1.0f, scale2);
    prep_x_kernel<<<(TB_ * IN_ + 255) / 256, 256>>>(x, xs);

    dim3 blk(256);
    dim3 gHid(H_ / 128, TB_ / 128);   // (8, 200)
    dim3 gOut(1, TB_ / 128);          // (1, 200)
    const int RS_BLK = (TB_ * 32 + 255) / 256;

    // ---- Layer 1 (fp32, R1-identical path)
    gemm_nt_kernel<<<gHid, blk>>>(xs, q1, cur, TB_, H_, IN_);
    lif_sub1_kernel<<<(B_ * H_ + 255) / 256, 256>>>(cur, spk1, spkb, 0.9f, B_ * H_);

    // ---- Layer 2: D1 = S@k^T (exact int), D2 = S@e^T (ref's q-rounding)
    gemm_hmma<128><<<gHid, blk, SM128>>>(spkb, w2k, cur,  TB_, H_, H_);
    gemm_hmma<128><<<gHid, blk, SM128>>>(spkb, w2e, cur2, TB_, H_, H_);
    rowsum_b_kernel<<<RS_BLK, 256>>>(spkb, R);
    lif_sub2_kernel<<<(B_ * H_ + 255) / 256, 256>>>(cur, cur2, R, spk2, spkb, 0.85f, scale2, 0.001f);

    // ---- Layer 3
    gemm_hmma<128><<<gHid, blk, SM128>>>(spkb, w3k, cur,  TB_, H_, H_);
    gemm_hmma<128><<<gHid, blk, SM128>>>(spkb, w3e, cur2, TB_, H_, H_);
    rowsum_b_kernel<<<RS_BLK, 256>>>(spkb, R);
    lif_sub2_kernel<<<(B_ * H_ + 255) / 256, 256>>>(cur, cur2, R, spk3, spkb, 0.8f, scale2, 0.001f);

    // ---- Layer 4 (N padded to 64)
    gemm_hmma<64><<<gOut, blk, SM64>>>(spkb, w4k, cur4,  TB_, 64, H_);
    gemm_hmma<64><<<gOut, blk, SM64>>>(spkb, w4e, cur4b, TB_, 64, H_);
    rowsum_b_kernel<<<RS_BLK, 256>>>(spkb, R);
    lif_zero2_kernel<<<(B_ * OUT_ + 255) / 256, 256>>>(cur4, cur4b, R, spk4, mem4, 0.95f, scale2, 0.001f);

    (void)in_sizes; (void)n_in; (void)out_size;
}

// round 8
// speedup vs baseline: 3.0089x; 1.0010x over previous
#include <cuda_runtime.h>
#include <cuda_bf16.h>
#include <cstddef>
#include <cstdint>

// Problem dims
#define B_    256
#define T_    100
#define IN_   128
#define H_    1024
#define OUT_  35
#define TB_   (B_ * T_)   // 25600 rows of the batched GEMMs

// ---------------- scratch (device globals; no allocation allowed) ----------
__device__ __align__(128) float         g_xs[(size_t)TB_ * IN_];   // [T,B,IN]/15 fp32
__device__ __align__(128) float         g_q1[H_ * IN_];            // layer-1 fp32 quant weights
__device__ __align__(128) __nv_bfloat16 g_w2k[H_ * H_];
__device__ __align__(128) __nv_bfloat16 g_w2e[H_ * H_];
__device__ __align__(128) __nv_bfloat16 g_w3k[H_ * H_];
__device__ __align__(128) __nv_bfloat16 g_w3e[H_ * H_];
__device__ __align__(128) __nv_bfloat16 g_w4k[128 * H_];           // rows 35..127 zero
__device__ __align__(128) __nv_bfloat16 g_w4e[128 * H_];
__device__ __align__(128) float         g_cur[(size_t)TB_ * H_];   // combined currents
__device__ __align__(128) __nv_bfloat16 g_spkb[(size_t)TB_ * H_];
__device__ __align__(128) float         g_R[TB_];

// ---------------- PTX helpers ----------------------------------------------
__device__ __forceinline__ uint32_t smem_u32(const void* p) {
    uint32_t a;
    asm("{ .reg .u64 t; cvta.to.shared.u64 t, %1; cvt.u32.u64 %0, t; }" : "=r"(a) : "l"(p));
    return a;
}
__device__ __forceinline__ void cp16(uint32_t s, const void* g) {
    asm volatile("cp.async.cg.shared.global [%0], [%1], 16;" :: "r"(s), "l"(g));
}
__device__ __forceinline__ void cp_commit() {
    asm volatile("cp.async.commit_group;" ::: "memory");
}
__device__ __forceinline__ void ldsm4(uint32_t& r0, uint32_t& r1, uint32_t& r2, uint32_t& r3,
                                      uint32_t a) {
    asm volatile("ldmatrix.sync.aligned.m8n8.x4.shared.b16 {%0,%1,%2,%3}, [%4];"
                 : "=r"(r0), "=r"(r1), "=r"(r2), "=r"(r3) : "r"(a));
}
__device__ __forceinline__ void mma16816(float* d, const uint32_t* a, const uint32_t* b) {
    asm volatile("mma.sync.aligned.m16n8k16.row.col.f32.bf16.bf16.f32 "
                 "{%0,%1,%2,%3}, {%4,%5,%6,%7}, {%8,%9}, {%0,%1,%2,%3};"
                 : "+f"(d[0]), "+f"(d[1]), "+f"(d[2]), "+f"(d[3])
                 : "r"(a[0]), "r"(a[1]), "r"(a[2]), "r"(a[3]), "r"(b[0]), "r"(b[1]));
}

// ---------------- fused dual-B HMMA GEMM (spike layers only) ---------------
// C[M, Nstr] tile = scale * (A @ Bk^T) + (A @ Be^T)
// BM=128, BN=128, BK=64 (128B swizzled rows). 512 threads = 16 warps,
// warp grid 2(m) x 8(n), warp tile 64x16 per accumulator set.
__global__ __launch_bounds__(512)
void gemm_dual(const __nv_bfloat16* __restrict__ A,
               const __nv_bfloat16* __restrict__ Bk,
               const __nv_bfloat16* __restrict__ Be,
               float* __restrict__ C, int Nstr, int K, float scale) {
    constexpr int STAGE = 3 * 16384;
    extern __shared__ __align__(1024) char smem[];
    const int tid = threadIdx.x;
    const int wid = tid >> 5, lid = tid & 31;
    const int row0 = blockIdx.y * 128, col0 = blockIdx.x * 128;
    const int wm = wid & 1, wn = wid >> 1;
    const int warpM0 = wm * 64;
    const int warpN0 = wn * 16;
    const uint32_t sb = smem_u32(smem);
    const int NCH = K / 64;

    float acc1[4][2][4], acc2[4][2][4];
#pragma unroll
    for (int i = 0; i < 4; i++)
#pragma unroll
        for (int j = 0; j < 2; j++)
#pragma unroll
            for (int c = 0; c < 4; c++) { acc1[i][j][c] = 0.0f; acc2[i][j][c] = 0.0f; }

    auto issue = [&](int i) {
        const int k0 = i * 64;
        const uint32_t base = sb + (i & 1) * STAGE;
#pragma unroll
        for (int p = 0; p < 2; p++) {
            int u = tid + p * 512;
            int r = u >> 3, c = u & 7;
            uint32_t sw = r * 128 + ((c ^ (r & 7)) << 4);
            cp16(base + sw,         A  + (size_t)(row0 + r) * K + k0 + c * 8);
            cp16(base + 16384 + sw, Bk + (size_t)(col0 + r) * K + k0 + c * 8);
            cp16(base + 32768 + sw, Be + (size_t)(col0 + r) * K + k0 + c * 8);
        }
        cp_commit();
    };

    issue(0);
    if (NCH > 1) issue(1);

    for (int i = 0; i < NCH; i++) {
        const uint32_t base = sb + (i & 1) * STAGE;
        if (i + 1 < NCH) asm volatile("cp.async.wait_group 1;" ::: "memory");
        else             asm volatile("cp.async.wait_group 0;" ::: "memory");
        __syncthreads();

#pragma unroll
        for (int j = 0; j < 4; j++) {
            uint32_t a[4][4], bk[2][2], be[2][2];
#pragma unroll
            for (int mf = 0; mf < 4; mf++) {
                int r = warpM0 + mf * 16 + (lid & 15);
                int c = 2 * j + (lid >> 4);
                ldsm4(a[mf][0], a[mf][1], a[mf][2], a[mf][3],
                      base + r * 128 + ((c ^ (r & 7)) << 4));
            }
            {
                int r = warpN0 + (lid & 7) + (((lid >> 4) & 1) << 3);
                int c = 2 * j + ((lid >> 3) & 1);
                uint32_t sw = r * 128 + ((c ^ (r & 7)) << 4);
                uint32_t t0, t1, t2, t3;
                ldsm4(t0, t1, t2, t3, base + 16384 + sw);
                bk[0][0] = t0; bk[0][1] = t1; bk[1][0] = t2; bk[1][1] = t3;
                ldsm4(t0, t1, t2, t3, base + 32768 + sw);
                be[0][0] = t0; be[0][1] = t1; be[1][0] = t2; be[1][1] = t3;
            }
#pragma unroll
            for (int mf = 0; mf < 4; mf++)
#pragma unroll
                for (int nf = 0; nf < 2; nf++) {
                    mma16816(acc1[mf][nf], a[mf], bk[nf]);
                    mma16816(acc2[mf][nf], a[mf], be[nf]);
                }
        }
        __syncthreads();
        if (i + 2 < NCH) issue(i + 2);
    }

    // epilogue: combined C = scale*acc1 + acc2
#pragma unroll
    for (int mf = 0; mf < 4; mf++) {
        int r = row0 + warpM0 + mf * 16 + (lid >> 2);
#pragma unroll
        for (int nf = 0; nf < 2; nf++) {
            int cc = col0 + warpN0 + nf * 8 + (lid & 3) * 2;
            float2 v0 = {fmaf(scale, acc1[mf][nf][0], acc2[mf][nf][0]),
                         fmaf(scale, acc1[mf][nf][1], acc2[mf][nf][1])};
            float2 v1 = {fmaf(scale, acc1[mf][nf][2], acc2[mf][nf][2]),
                         fmaf(scale, acc1[mf][nf][3], acc2[mf][nf][3])};
            *(float2*)&C[(size_t)r * Nstr + cc]       = v0;
            *(float2*)&C[(size_t)(r + 8) * Nstr + cc] = v1;
        }
    }
}

// ---------------- fp32 SGEMM for layer 1 (R6-proven, 0 spike flips) --------
#define BM 128
#define BN1 128
#define BK 16
__global__ __launch_bounds__(256)
void gemm_nt_kernel(const float* __restrict__ A, const float* __restrict__ W,
                    float* __restrict__ C, int M, int N, int K) {
    __shared__ float As[BK][BM];
    __shared__ float Ws[BK][BN1];
    const int tid  = threadIdx.x;
    const int tr   = tid >> 4;
    const int tc   = tid & 15;
    const int row0 = blockIdx.y * BM;
    const int col0 = blockIdx.x * BN1;

    float acc[8][8];
#pragma unroll
    for (int i = 0; i < 8; i++)
#pragma unroll
        for (int j = 0; j < 8; j++) acc[i][j] = 0.0f;

    for (int k0 = 0; k0 < K; k0 += BK) {
#pragma unroll
        for (int l = 0; l < 2; l++) {
            int lin = tid + l * 256;
            int r = lin >> 2, c4 = (lin & 3) << 2;
            float4 v = *(const float4*)&A[(size_t)(row0 + r) * K + k0 + c4];
            As[c4 + 0][r] = v.x; As[c4 + 1][r] = v.y;
            As[c4 + 2][r] = v.z; As[c4 + 3][r] = v.w;
        }
#pragma unroll
        for (int l = 0; l < 2; l++) {
            int lin = tid + l * 256;
            int r = lin >> 2, c4 = (lin & 3) << 2;
            float4 v = *(const float4*)&W[(size_t)(col0 + r) * K + k0 + c4];
            Ws[c4 + 0][r] = v.x; Ws[c4 + 1][r] = v.y;
            Ws[c4 + 2][r] = v.z; Ws[c4 + 3][r] = v.w;
        }
        __syncthreads();
#pragma unroll
        for (int k = 0; k < BK; k++) {
            float4 a0 = *(const float4*)&As[k][tr * 8];
            float4 a1 = *(const float4*)&As[k][tr * 8 + 4];
            float4 b0 = *(const float4*)&Ws[k][tc * 8];
            float4 b1 = *(const float4*)&Ws[k][tc * 8 + 4];
            float a[8] = {a0.x, a0.y, a0.z, a0.w, a1.x, a1.y, a1.z, a1.w};
            float b[8] = {b0.x, b0.y, b0.z, b0.w, b1.x, b1.y, b1.z, b1.w};
#pragma unroll
            for (int i = 0; i < 8; i++)
#pragma unroll
                for (int j = 0; j < 8; j++)
                    acc[i][j] = fmaf(a[i], b[j], acc[i][j]);
        }
        __syncthreads();
    }
#pragma unroll
    for (int i = 0; i < 8; i++) {
        int row = row0 + tr * 8 + i;
#pragma unroll
        for (int j = 0; j < 8; j++)
            C[(size_t)row * N + col0 + tc * 8 + j] = acc[i][j];
    }
}

// ---------------- quant kernels --------------------------------------------
__global__ void quant_kernel(const float* __restrict__ w, float* __restrict__ q,
                             int n, float wmin, float wmax, float scale) {
    int i = blockIdx.x * blockDim.x + threadIdx.x;
    if (i >= n) return;
    float wc = fminf(fmaxf(w[i], wmin), wmax);
    float t  = __fdiv_rn(__fsub_rn(wc, wmin), scale);
    q[i] = __fadd_rn(__fmul_rn(rintf(t), scale), wmin);
}

// k index (bf16 exact) + e = q - (wmin + k*scale) in DOUBLE, then bf16.
__global__ void quantke_kernel(const float* __restrict__ w,
                               __nv_bfloat16* __restrict__ kq, __nv_bfloat16* __restrict__ eq,
                               int n, int nsrc, float wmin, float wmax, float scale) {
    int i = blockIdx.x * blockDim.x + threadIdx.x;
    if (i >= n) return;
    float kf = 0.0f, e = 0.0f;
    if (i < nsrc) {
        float wc = fminf(fmaxf(w[i], wmin), wmax);
        kf = rintf(__fdiv_rn(__fsub_rn(wc, wmin), scale));
        float q = __fadd_rn(__fmul_rn(kf, scale), wmin);
        double ed = (double)q - (double)wmin - (double)scale * (double)kf;
        e = (float)ed;
    }
    kq[i] = __float2bfloat16_rn(kf);
    eq[i] = __float2bfloat16_rn(e);
}

// ---------------- x: [B,T,IN] -> [T,B,IN]/15 (fp32, R1/R6-identical) -------
__global__ void prep_x_kernel(const float* __restrict__ x, float* __restrict__ xs) {
    int idx = blockIdx.x * blockDim.x + threadIdx.x;
    if (idx >= TB_ * IN_) return;
    int i  = idx % IN_;
    int rb = idx / IN_;
    int b  = rb % B_;
    int t  = rb / B_;
    xs[idx] = __fdiv_rn(x[((size_t)b * T_ + t) * IN_ + i], 15.0f);
}

// ---------------- rowsum of bf16 spikes (exact integers) -------------------
__global__ void rowsum_b_kernel(const __nv_bfloat16* __restrict__ S, float* __restrict__ R) {
    int w = (blockIdx.x * blockDim.x + threadIdx.x) >> 5;
    int l = threadIdx.x & 31;
    if (w >= TB_) return;
    const uint4* p = (const uint4*)(S + (size_t)w * H_);
    float s = 0.0f;
#pragma unroll
    for (int i = 0; i < 4; i++) {
        uint4 v = p[l + i * 32];
        const __nv_bfloat16* h = (const __nv_bfloat16*)&v;
#pragma unroll
        for (int c = 0; c < 8; c++) s += __bfloat162float(h[c]);
    }
#pragma unroll
    for (int o = 16; o; o >>= 1) s += __shfl_xor_sync(0xffffffffu, s, o);
    if (l == 0) R[w] = s;
}

// ---------------- LIF scans ------------------------------------------------
// Layer 1: direct fp32 currents (R6-identical)
__global__ void lif_sub1_kernel(const float* __restrict__ cur, float* __restrict__ spk,
                                __nv_bfloat16* __restrict__ spkb, float beta, int n) {
    int idx = blockIdx.x * blockDim.x + threadIdx.x;
    if (idx >= n) return;
    float m = 0.0f;
    for (int t = 0; t < T_; t++) {
        float c     = cur[(size_t)t * n + idx];
        float reset = (m > 1.0f) ? 1.0f : 0.0f;
        float base  = __fadd_rn(__fmul_rn(beta, m), c);
        m = base - reset;
        float s = (m > 1.0f) ? 1.0f : 0.0f;
        spk[(size_t)t * n + idx]  = s;
        spkb[(size_t)t * n + idx] = __float2bfloat16_rn(s);
    }
}

// Hidden layers: c = D + wmin*R  (D already = scale*Dk + De from fused epilogue)
__global__ void lif_sub_kernel(const float* __restrict__ D, const float* __restrict__ R,
                               float* __restrict__ spk, __nv_bfloat16* __restrict__ spkb,
                               float beta, float wmin) {
    int idx = blockIdx.x * blockDim.x + threadIdx.x;
    if (idx >= B_ * H_) return;
    int b = idx / H_, h = idx % H_;
    float m = 0.0f;
    for (int t = 0; t < T_; t++) {
        size_t mm = (size_t)t * B_ + b;
        float c = fmaf(wmin, R[mm], D[mm * H_ + h]);
        float reset = (m > 1.0f) ? 1.0f : 0.0f;
        float base  = __fadd_rn(__fmul_rn(beta, m), c);
        m = base - reset;
        float s = (m > 1.0f) ? 1.0f : 0.0f;
        spk[(size_t)t * (B_ * H_) + idx]  = s;
        spkb[(size_t)t * (B_ * H_) + idx] = __float2bfloat16_rn(s);
    }
}

__global__ void lif_zero_kernel(const float* __restrict__ D, const float* __restrict__ R,
                                float* __restrict__ spk, float* __restrict__ mem,
                                float beta, float wmin) {
    int idx = blockIdx.x * blockDim.x + threadIdx.x;
    if (idx >= B_ * OUT_) return;
    int b = idx / OUT_, h = idx % OUT_;
    float m = 0.0f;
    for (int t = 0; t < T_; t++) {
        size_t mm = (size_t)t * B_ + b;
        float c = fmaf(wmin, R[mm], D[mm * 128 + h]);
        bool  rst  = (m > 1.0f);
        float base = __fadd_rn(__fmul_rn(beta, m), c);
        m = rst ? 0.0f : base;
        spk[(size_t)t * (B_ * OUT_) + idx] = (m > 1.0f) ? 1.0f : 0.0f;
        mem[(size_t)t * (B_ * OUT_) + idx] = m;
    }
}

// ---------------------------------------------------------------------------
extern "C" void kernel_launch(void* const* d_in, const int* in_sizes, int n_in,
                              void* d_out, int out_size) {
    const float* x  = (const float*)d_in[0];
    const float* w1 = (const float*)d_in[1];
    const float* w2 = (const float*)d_in[2];
    const float* w3 = (const float*)d_in[3];
    const float* w4 = (const float*)d_in[4];
    float* out = (float*)d_out;

    float *xs, *q1, *cur, *R;
    __nv_bfloat16 *w2k, *w2e, *w3k, *w3e, *w4k, *w4e, *spkb;
    cudaGetSymbolAddress((void**)&xs, g_xs);   cudaGetSymbolAddress((void**)&q1, g_q1);
    cudaGetSymbolAddress((void**)&w2k, g_w2k); cudaGetSymbolAddress((void**)&w2e, g_w2e);
    cudaGetSymbolAddress((void**)&w3k, g_w3k); cudaGetSymbolAddress((void**)&w3e, g_w3e);
    cudaGetSymbolAddress((void**)&w4k, g_w4k); cudaGetSymbolAddress((void**)&w4e, g_w4e);
    cudaGetSymbolAddress((void**)&cur, g_cur);
    cudaGetSymbolAddress((void**)&spkb, g_spkb);
    cudaGetSymbolAddress((void**)&R, g_R);

    const size_t SPK  = (size_t)TB_ * H_;
    const size_t SPK4 = (size_t)TB_ * OUT_;
    float* spk1 = out;
    float* spk2 = out + SPK;
    float* spk3 = out + 2 * SPK;
    float* spk4 = out + 3 * SPK;
    float* mem4 = out + 3 * SPK + SPK4;

    const float scale1 = (float)((0.5 - (-0.5)) / 15.0);
    const float scale2 = (float)((1.0 - 0.001) / 15.0);

    const int SMEM = 2 * 3 * 16384;   // 98304
    cudaFuncSetAttribute(gemm_dual, cudaFuncAttributeMaxDynamicSharedMemorySize, SMEM);

    // ---- prep
    quant_kernel<<<(H_ * IN_ + 255) / 256, 256>>>(w1, q1, H_ * IN_, -0.5f, 0.5f, scale1);
    quantke_kernel<<<(H_ * H_ + 255) / 256, 256>>>(w2, w2k, w2e, H_ * H_, H_ * H_, 0.001f, 1.0f, scale2);
    quantke_kernel<<<(H_ * H_ + 255) / 256, 256>>>(w3, w3k, w3e, H_ * H_, H_ * H_, 0.001f, 1.0f, scale2);
    quantke_kernel<<<(128 * H_ + 255) / 256, 256>>>(w4, w4k, w4e, 128 * H_, OUT_ * H_, 0.001f, 1.0f, scale2);
    prep_x_kernel<<<(TB_ * IN_ + 255) / 256, 256>>>(x, xs);

    dim3 gHid(H_ / 128, TB_ / 128);   // (8, 200)
    dim3 gOut(1, TB_ / 128);          // (1, 200)
    const int RS_BLK = (TB_ * 32 + 255) / 256;

    // ---- Layer 1 (fp32, R6-proven path)
    gemm_nt_kernel<<<gHid, 256>>>(xs, q1, cur, TB_, H_, IN_);
    lif_sub1_kernel<<<(B_ * H_ + 255) / 256, 256>>>(cur, spk1, spkb, 0.9f, B_ * H_);

    // ---- Layer 2 (fused k+e dual GEMM)
    rowsum_b_kernel<<<RS_BLK, 256>>>(spkb, R);
    gemm_dual<<<gHid, 512, SMEM>>>(spkb, w2k, w2e, cur, H_, H_, scale2);
    lif_sub_kernel<<<(B_ * H_ + 255) / 256, 256>>>(cur, R, spk2, spkb, 0.85f, 0.001f);

    // ---- Layer 3
    rowsum_b_kernel<<<RS_BLK, 256>>>(spkb, R);
    gemm_dual<<<gHid, 512, SMEM>>>(spkb, w3k, w3e, cur, H_, H_, scale2);
    lif_sub_kernel<<<(B_ * H_ + 255) / 256, 256>>>(cur, R, spk3, spkb, 0.8f, 0.001f);

    // ---- Layer 4 (N padded to 128)
    rowsum_b_kernel<<<RS_BLK, 256>>>(spkb, R);
    gemm_dual<<<gOut, 512, SMEM>>>(spkb, w4k, w4e, cur, 128, H_, scale2);
    lif_zero_kernel<<<(B_ * OUT_ + 255) / 256, 256>>>(cur, R, spk4, mem4, 0.95f, 0.001f);

    (void)in_sizes; (void)n_in; (void)out_size;
}